// round 12
// baseline (speedup 1.0000x reference)
#include <cuda_runtime.h>
#include <cstdint>

#define N_BATCH 4
#define PSUPER 256                /* p rows per block (2 x 128-row tiles) */
#define QTILE 128                 /* q cols per block */
#define NQT 32                    /* 4096/128 q tiles */
#define NST 16                    /* 4096/256 p supertiles */
#define CELLS 272                 /* sum_{S=0}^{15} (32-2S) */
#define TOTALB (CELLS*N_BATCH)
#define BLOCK 256
#define ASTR 264                  /* %32==8 -> conflict-free frag loads */
#define BSTR 136
#define SLOTS 28                  /* 24 D-slots + 4 G-slots */

__device__ double g_acc;
__device__ unsigned int g_done;

// prefix[S] = 32S - S(S-1)
__constant__ int c_pre[17] = {0,32,62,90,116,140,162,182,200,216,230,242,252,260,266,270,272};

__device__ __forceinline__ float ex2f(float a) {
    float r; asm("ex2.approx.ftz.f32 %0, %1;" : "=f"(r) : "f"(a)); return r;
}
__device__ __forceinline__ float tf32r(float v) {
    uint32_t u; asm("cvt.rna.tf32.f32 %0, %1;" : "=r"(u) : "f"(v));
    return __uint_as_float(u);
}
__device__ __forceinline__ void mma8(float& d0, float& d1, float& d2, float& d3,
                                     uint32_t a0, uint32_t a1, uint32_t a2, uint32_t a3,
                                     uint32_t b0, uint32_t b1) {
    asm("mma.sync.aligned.m16n8k8.row.col.f32.tf32.tf32.f32 "
        "{%0,%1,%2,%3}, {%4,%5,%6,%7}, {%8,%9}, {%0,%1,%2,%3};"
        : "+f"(d0), "+f"(d1), "+f"(d2), "+f"(d3)
        : "r"(a0), "r"(a1), "r"(a2), "r"(a3), "r"(b0), "r"(b1));
}

// f[10] = {fx,fy,fr,fg,fb,h,s0,s1,s2,s3}; features pre-scaled by sqrt(log2 e),
// h = -0.5*||f_scaled||^2 so exp(-0.5 d^2) == ex2(h_p + h_q + f_p.f_q).
__device__ __forceinline__ void compute_pt(const float* __restrict__ img,
                                           const float* __restrict__ sg,
                                           int p, float* f) {
    const float SQL2E = 1.2011224087864498f;
    int y = p >> 6, x = p & 63;
    int ro = (y << 8) + (x << 1);
    float fx = (float)x * (SQL2E / 50.0f);
    float fy = (float)y * (SQL2E / 50.0f);
    float fr = img[ro]         * (SQL2E / 15.0f);
    float fg = img[16384 + ro] * (SQL2E / 15.0f);
    float fb = img[32768 + ro] * (SQL2E / 15.0f);
    float h  = -0.5f * (fx*fx + fy*fy + fr*fr + fg*fg + fb*fb);
    f[0]=fx; f[1]=fy; f[2]=fr; f[3]=fg; f[4]=fb; f[5]=h;
#pragma unroll
    for (int k = 0; k < 4; k++) {
        const float* sk = sg + k * 16384;
        f[6+k] = (sk[ro] + sk[ro+1] + sk[ro+128] + sk[ro+129]) * 0.25f;
    }
}

__global__ void __launch_bounds__(BLOCK) crf_kernel(const float* __restrict__ images,
                                                    const float* __restrict__ segs,
                                                    float* __restrict__ out) {
    __shared__ float sFA[SLOTS * ASTR];   // p supertile, slot-major (29.6 KB)
    __shared__ float sFB[SLOTS * BSTR];   // q tile (15.2 KB)
    __shared__ float wsum[BLOCK / 32];

    int tid  = threadIdx.x;
    int w    = tid >> 5;
    int lane = tid & 31;
    int g    = lane & 3;
    int r    = lane >> 2;
    int n = blockIdx.y;

    // decode cell t -> (S supertile, J q-tile), J >= 2S
    int t = blockIdx.x;
    int S = 0;
#pragma unroll
    for (int s = 1; s < NST; s++)
        if (t >= c_pre[s]) S = s;
    int J = 2 * S + (t - c_pre[S]);

    const float* img = images + (size_t)n * 3 * 16384;
    const float* sg  = segs   + (size_t)n * 4 * 16384;

    // ---- prologue: A side = 256 p points (1/thread), B side = 128 q points (tid<128) ----
    {
        float f[10];
        compute_pt(img, sg, S * PSUPER + tid, f);
        float hi[5], lo[5];
#pragma unroll
        for (int d = 0; d < 5; d++) { hi[d] = tf32r(f[d]); lo[d] = tf32r(f[d] - hi[d]); }
        float hh = tf32r(f[5]), hl = tf32r(f[5] - hh);
        // A D-slots: 0-4 hi, 5-9 hi, 10-14 lo, 15 h_hi, 16 h_lo, 17 1, 18 1, 19-23 0
#pragma unroll
        for (int d = 0; d < 5; d++) {
            sFA[d * ASTR + tid]        = hi[d];
            sFA[(5 + d) * ASTR + tid]  = hi[d];
            sFA[(10 + d) * ASTR + tid] = lo[d];
        }
        sFA[15 * ASTR + tid] = hh;
        sFA[16 * ASTR + tid] = hl;
        sFA[17 * ASTR + tid] = 1.0f;
        sFA[18 * ASTR + tid] = 1.0f;
#pragma unroll
        for (int k = 19; k < 24; k++) sFA[k * ASTR + tid] = 0.0f;
#pragma unroll
        for (int k = 0; k < 4; k++) sFA[(24 + k) * ASTR + tid] = tf32r(f[6 + k]);
    }
    if (tid < QTILE) {
        float f[10];
        compute_pt(img, sg, J * QTILE + tid, f);
        float hi[5], lo[5];
#pragma unroll
        for (int d = 0; d < 5; d++) { hi[d] = tf32r(f[d]); lo[d] = tf32r(f[d] - hi[d]); }
        float hh = tf32r(f[5]), hl = tf32r(f[5] - hh);
        // B D-slots: 0-4 hi, 5-9 lo, 10-14 hi, 15 1, 16 1, 17 h_hi, 18 h_lo, 19-23 0
#pragma unroll
        for (int d = 0; d < 5; d++) {
            sFB[d * BSTR + tid]        = hi[d];
            sFB[(5 + d) * BSTR + tid]  = lo[d];
            sFB[(10 + d) * BSTR + tid] = hi[d];
        }
        sFB[15 * BSTR + tid] = 1.0f;
        sFB[16 * BSTR + tid] = 1.0f;
        sFB[17 * BSTR + tid] = hh;
        sFB[18 * BSTR + tid] = hl;
#pragma unroll
        for (int k = 19; k < 24; k++) sFB[k * BSTR + tid] = 0.0f;
#pragma unroll
        for (int k = 0; k < 4; k++) sFB[(24 + k) * BSTR + tid] = tf32r(f[6 + k]);
    }
    __syncthreads();

    // row-tile weight: warps 0-3 -> tile 2S, warps 4-7 -> tile 2S+1
    float wt;
    if (w < 4) wt = (J == 2 * S) ? 1.0f : 2.0f;
    else       wt = (J == 2 * S) ? 0.0f : ((J == 2 * S + 1) ? 1.0f : 2.0f);

    float acc = 0.0f;

    if (wt != 0.0f) {
        int base = 32 * w;   // 32 p-rows per warp: row-blocks at base, base+16

        // A fragments: 2 row-blocks x 3 k-steps x 4 regs, + G frags
        uint32_t A0[3][4], A1[3][4];
#pragma unroll
        for (int ks = 0; ks < 3; ks++) {
            int k0 = 8 * ks;
            A0[ks][0] = __float_as_uint(sFA[(k0 + g) * ASTR + base + r]);
            A0[ks][1] = __float_as_uint(sFA[(k0 + g) * ASTR + base + r + 8]);
            A0[ks][2] = __float_as_uint(sFA[(k0 + g + 4) * ASTR + base + r]);
            A0[ks][3] = __float_as_uint(sFA[(k0 + g + 4) * ASTR + base + r + 8]);
            A1[ks][0] = __float_as_uint(sFA[(k0 + g) * ASTR + base + 16 + r]);
            A1[ks][1] = __float_as_uint(sFA[(k0 + g) * ASTR + base + 16 + r + 8]);
            A1[ks][2] = __float_as_uint(sFA[(k0 + g + 4) * ASTR + base + 16 + r]);
            A1[ks][3] = __float_as_uint(sFA[(k0 + g + 4) * ASTR + base + 16 + r + 8]);
        }
        uint32_t GA00 = __float_as_uint(sFA[(24 + g) * ASTR + base + r]);
        uint32_t GA01 = __float_as_uint(sFA[(24 + g) * ASTR + base + r + 8]);
        uint32_t GA10 = __float_as_uint(sFA[(24 + g) * ASTR + base + 16 + r]);
        uint32_t GA11 = __float_as_uint(sFA[(24 + g) * ASTR + base + 16 + r + 8]);

#pragma unroll 2
        for (int j = 0; j < 16; j++) {
            int n0 = 8 * j;
            // B fragments once per j, shared by both row-blocks
            uint32_t b[3][2];
#pragma unroll
            for (int ks = 0; ks < 3; ks++) {
                int k0 = 8 * ks;
                b[ks][0] = __float_as_uint(sFB[(k0 + g) * BSTR + n0 + r]);
                b[ks][1] = __float_as_uint(sFB[(k0 + g + 4) * BSTR + n0 + r]);
            }
            uint32_t gb = __float_as_uint(sFB[(24 + g) * BSTR + n0 + r]);

            // row-block 0
            {
                float d0=0.f, d1=0.f, d2=0.f, d3=0.f;
#pragma unroll
                for (int ks = 0; ks < 3; ks++)
                    mma8(d0, d1, d2, d3, A0[ks][0], A0[ks][1], A0[ks][2], A0[ks][3], b[ks][0], b[ks][1]);
                float g0=0.f, g1=0.f, g2=0.f, g3=0.f;
                mma8(g0, g1, g2, g3, GA00, GA01, 0u, 0u, gb, 0u);
                acc = fmaf(ex2f(d0), g0, acc);
                acc = fmaf(ex2f(d1), g1, acc);
                acc = fmaf(ex2f(d2), g2, acc);
                acc = fmaf(ex2f(d3), g3, acc);
            }
            // row-block 1
            {
                float d0=0.f, d1=0.f, d2=0.f, d3=0.f;
#pragma unroll
                for (int ks = 0; ks < 3; ks++)
                    mma8(d0, d1, d2, d3, A1[ks][0], A1[ks][1], A1[ks][2], A1[ks][3], b[ks][0], b[ks][1]);
                float g0=0.f, g1=0.f, g2=0.f, g3=0.f;
                mma8(g0, g1, g2, g3, GA10, GA11, 0u, 0u, gb, 0u);
                acc = fmaf(ex2f(d0), g0, acc);
                acc = fmaf(ex2f(d1), g1, acc);
                acc = fmaf(ex2f(d2), g2, acc);
                acc = fmaf(ex2f(d3), g3, acc);
            }
        }
        acc *= wt;
    }

    // warp + block reduce, one double atomic per block
#pragma unroll
    for (int off = 16; off > 0; off >>= 1)
        acc += __shfl_down_sync(0xFFFFFFFFu, acc, off);
    if (lane == 0) wsum[w] = acc;
    __syncthreads();
    if (tid == 0) {
        float s = 0.0f;
#pragma unroll
        for (int i = 0; i < BLOCK / 32; i++) s += wsum[i];
        atomicAdd(&g_acc, (double)s);
        __threadfence();
        unsigned int d = atomicAdd(&g_done, 1u);
        if (d == TOTALB - 1u) {
            double total = *((volatile double*)&g_acc);
            out[0] = (float)(total * (-1e-7 / (double)N_BATCH));
            g_acc = 0.0;          // reset for next graph replay
            g_done = 0u;
        }
    }
}

extern "C" void kernel_launch(void* const* d_in, const int* in_sizes, int n_in,
                              void* d_out, int out_size) {
    const float* images = (const float*)d_in[0];
    const float* segs   = (const float*)d_in[1];
    dim3 grid(CELLS, N_BATCH);
    crf_kernel<<<grid, BLOCK>>>(images, segs, (float*)d_out);
}

// round 13
// speedup vs baseline: 1.4330x; 1.4330x over previous
#include <cuda_runtime.h>
#include <cstdint>

#define N_BATCH 4
#define PTILE 128
#define NTILES 32                 /* 4096/128 */
#define CELLS 528                 /* upper-triangle tile pairs */
#define TOTALB (CELLS*N_BATCH)
#define BLOCK 256
#define FSTR 136                  /* smem row stride (floats); %32==8 -> conflict-free */
#define SLOTS 20                  /* 16 D-slots (15 live + 1 zero) + 4 G-slots */

__device__ double g_acc;
__device__ unsigned int g_done;

__device__ __forceinline__ float ex2f(float a) {
    float r; asm("ex2.approx.ftz.f32 %0, %1;" : "=f"(r) : "f"(a)); return r;
}
__device__ __forceinline__ float tf32r(float v) {
    uint32_t u; asm("cvt.rna.tf32.f32 %0, %1;" : "=r"(u) : "f"(v));
    return __uint_as_float(u);
}
__device__ __forceinline__ void mma8(float& d0, float& d1, float& d2, float& d3,
                                     uint32_t a0, uint32_t a1, uint32_t a2, uint32_t a3,
                                     uint32_t b0, uint32_t b1) {
    asm("mma.sync.aligned.m16n8k8.row.col.f32.tf32.tf32.f32 "
        "{%0,%1,%2,%3}, {%4,%5,%6,%7}, {%8,%9}, {%0,%1,%2,%3};"
        : "+f"(d0), "+f"(d1), "+f"(d2), "+f"(d3)
        : "r"(a0), "r"(a1), "r"(a2), "r"(a3), "r"(b0), "r"(b1));
}

// f[10] = {fx,fy,fr,fg,fb,h,s0,s1,s2,s3}; features pre-scaled by sqrt(log2 e),
// h = -0.5*||f_scaled||^2 so exp(-0.5 d^2) == ex2(h_p + h_q + f_p.f_q).
__device__ __forceinline__ void compute_pt(const float* __restrict__ img,
                                           const float* __restrict__ sg,
                                           int p, float* f) {
    const float SQL2E = 1.2011224087864498f;
    int y = p >> 6, x = p & 63;
    int ro = (y << 8) + (x << 1);
    float fx = (float)x * (SQL2E / 50.0f);
    float fy = (float)y * (SQL2E / 50.0f);
    float fr = img[ro]         * (SQL2E / 15.0f);
    float fg = img[16384 + ro] * (SQL2E / 15.0f);
    float fb = img[32768 + ro] * (SQL2E / 15.0f);
    float h  = -0.5f * (fx*fx + fy*fy + fr*fr + fg*fg + fb*fb);
    f[0]=fx; f[1]=fy; f[2]=fr; f[3]=fg; f[4]=fb; f[5]=h;
#pragma unroll
    for (int k = 0; k < 4; k++) {
        const float* sk = sg + k * 16384;
        f[6+k] = (sk[ro] + sk[ro+1] + sk[ro+128] + sk[ro+129]) * 0.25f;
    }
}

__global__ void __launch_bounds__(BLOCK) crf_kernel(const float* __restrict__ images,
                                                    const float* __restrict__ segs,
                                                    float* __restrict__ out) {
    __shared__ float sFA[SLOTS * FSTR];   // p-tile slots (10.9 KB)
    __shared__ float sFB[SLOTS * FSTR];   // q-tile slots
    __shared__ float sHA[PTILE];          // h_p, full fp32
    __shared__ float sHB[PTILE];          // h_q
    __shared__ float wsum[BLOCK / 32];

    int tid  = threadIdx.x;
    int w    = tid >> 5;
    int lane = tid & 31;
    int g    = lane & 3;    // frag column group
    int r    = lane >> 2;   // frag row
    int n = blockIdx.y;

    // decode upper-triangle cell t -> (I, J), J >= I
    int t = blockIdx.x;
    float ft = (float)t;
    int I = (int)((2.0f*NTILES + 1.0f - sqrtf((2.0f*NTILES+1.0f)*(2.0f*NTILES+1.0f) - 8.0f*ft)) * 0.5f);
    while (I * NTILES - (I * (I - 1)) / 2 > t) I--;
    while ((I + 1) * NTILES - ((I + 1) * I) / 2 <= t) I++;
    int J = I + (t - (I * NTILES - (I * (I - 1)) / 2));

    const float* img = images + (size_t)n * 3 * 16384;
    const float* sg  = segs   + (size_t)n * 4 * 16384;

    // ---- fill tiles: tid<128 -> p side (A), tid>=128 -> q side (B) ----
    // D-slots (K=16): A: 0-4 p_hi, 5-9 p_hi, 10-14 p_lo, 15 0
    //                 B: 0-4 q_hi, 5-9 q_lo, 10-14 q_hi, 15 0
    //   => dot = hi.hi + hi.lo + lo.hi   (lo.lo ~2^-22 dropped)
    // G-slots 16-19: seg vector (tf32). h kept OUT of MMA (added at c-init).
    {
        int side = tid >> 7;          // 0 = A(p), 1 = B(q)
        int idx  = tid & 127;
        float f[10];
        compute_pt(img, sg, (side ? J : I) * PTILE + idx, f);
        float* F = side ? sFB : sFA;

        float hi[5], lo[5];
#pragma unroll
        for (int d = 0; d < 5; d++) {
            hi[d] = tf32r(f[d]);
            lo[d] = tf32r(f[d] - hi[d]);
        }
        if (side == 0) {
#pragma unroll
            for (int d = 0; d < 5; d++) {
                F[d * FSTR + idx]        = hi[d];
                F[(5 + d) * FSTR + idx]  = hi[d];
                F[(10 + d) * FSTR + idx] = lo[d];
            }
            sHA[idx] = f[5];
        } else {
#pragma unroll
            for (int d = 0; d < 5; d++) {
                F[d * FSTR + idx]        = hi[d];
                F[(5 + d) * FSTR + idx]  = lo[d];
                F[(10 + d) * FSTR + idx] = hi[d];
            }
            sHB[idx] = f[5];
        }
        F[15 * FSTR + idx] = 0.0f;
#pragma unroll
        for (int k = 0; k < 4; k++)
            F[(16 + k) * FSTR + idx] = tf32r(f[6 + k]);
    }
    __syncthreads();

    // ---- per-warp: p-rows [16w, 16w+16), all q via 16 n-chunks of 8 ----
    int base = 16 * w;

    // D A-fragments (2 k-steps), loaded once
    uint32_t A[2][4];
#pragma unroll
    for (int ks = 0; ks < 2; ks++) {
        int k0 = 8 * ks;
        A[ks][0] = __float_as_uint(sFA[(k0 + g) * FSTR + base + r]);
        A[ks][1] = __float_as_uint(sFA[(k0 + g) * FSTR + base + r + 8]);
        A[ks][2] = __float_as_uint(sFA[(k0 + g + 4) * FSTR + base + r]);
        A[ks][3] = __float_as_uint(sFA[(k0 + g + 4) * FSTR + base + r + 8]);
    }
    // G A-fragments (k-slots 16-19 live; upper half zeroed via literal regs)
    uint32_t GA0 = __float_as_uint(sFA[(16 + g) * FSTR + base + r]);
    uint32_t GA1 = __float_as_uint(sFA[(16 + g) * FSTR + base + r + 8]);

    float hp0 = sHA[base + r];
    float hp1 = sHA[base + r + 8];

    float acc = 0.0f;

#pragma unroll 4
    for (int j = 0; j < 16; j++) {
        int n0 = 8 * j;

        // c-init with the h borders (cols 2g, 2g+1 of this n-chunk)
        float2 hq = *(const float2*)&sHB[n0 + 2 * g];
        float d0 = hp0 + hq.x;
        float d1 = hp0 + hq.y;
        float d2 = hp1 + hq.x;
        float d3 = hp1 + hq.y;

#pragma unroll
        for (int ks = 0; ks < 2; ks++) {
            int k0 = 8 * ks;
            uint32_t b0 = __float_as_uint(sFB[(k0 + g) * FSTR + n0 + r]);
            uint32_t b1 = __float_as_uint(sFB[(k0 + g + 4) * FSTR + n0 + r]);
            mma8(d0, d1, d2, d3, A[ks][0], A[ks][1], A[ks][2], A[ks][3], b0, b1);
        }

        // G = seg Gram (same c-frag positions)
        float g0 = 0.f, g1 = 0.f, g2 = 0.f, g3 = 0.f;
        {
            uint32_t gb0 = __float_as_uint(sFB[(16 + g) * FSTR + n0 + r]);
            mma8(g0, g1, g2, g3, GA0, GA1, 0u, 0u, gb0, 0u);
        }

        acc = fmaf(ex2f(d0), g0, acc);
        acc = fmaf(ex2f(d1), g1, acc);
        acc = fmaf(ex2f(d2), g2, acc);
        acc = fmaf(ex2f(d3), g3, acc);
    }

    if (I != J) acc *= 2.0f;   // symmetric off-diagonal cell

    // warp + block reduce, one double atomic per block
#pragma unroll
    for (int off = 16; off > 0; off >>= 1)
        acc += __shfl_down_sync(0xFFFFFFFFu, acc, off);
    if (lane == 0) wsum[w] = acc;
    __syncthreads();
    if (tid == 0) {
        float s = 0.0f;
#pragma unroll
        for (int i = 0; i < BLOCK / 32; i++) s += wsum[i];
        atomicAdd(&g_acc, (double)s);
        __threadfence();
        unsigned int d = atomicAdd(&g_done, 1u);
        if (d == TOTALB - 1u) {
            double total = *((volatile double*)&g_acc);
            out[0] = (float)(total * (-1e-7 / (double)N_BATCH));
            g_acc = 0.0;          // reset for next graph replay
            g_done = 0u;
        }
    }
}

extern "C" void kernel_launch(void* const* d_in, const int* in_sizes, int n_in,
                              void* d_out, int out_size) {
    const float* images = (const float*)d_in[0];
    const float* segs   = (const float*)d_in[1];
    dim3 grid(CELLS, N_BATCH);
    crf_kernel<<<grid, BLOCK>>>(images, segs, (float*)d_out);
}

// round 14
// speedup vs baseline: 1.5333x; 1.0700x over previous
#include <cuda_runtime.h>
#include <cstdint>

#define N_BATCH 4
#define PTILE 128
#define NTILES 32                 /* 4096/128 */
#define CELLS 528                 /* upper-triangle tile pairs */
#define TOTALB (CELLS*N_BATCH)
#define BLOCK 128
#define FSTR 136                  /* smem row stride (floats); %32==8 -> conflict-free */
#define SLOTS 20                  /* 16 D-slots (15 live + 1 zero) + 4 G-slots */

__device__ double g_acc;
__device__ unsigned int g_done;

__device__ __forceinline__ float ex2f(float a) {
    float r; asm("ex2.approx.ftz.f32 %0, %1;" : "=f"(r) : "f"(a)); return r;
}
__device__ __forceinline__ float tf32r(float v) {
    uint32_t u; asm("cvt.rna.tf32.f32 %0, %1;" : "=r"(u) : "f"(v));
    return __uint_as_float(u);
}
__device__ __forceinline__ void mma8(float& d0, float& d1, float& d2, float& d3,
                                     uint32_t a0, uint32_t a1, uint32_t a2, uint32_t a3,
                                     uint32_t b0, uint32_t b1) {
    asm("mma.sync.aligned.m16n8k8.row.col.f32.tf32.tf32.f32 "
        "{%0,%1,%2,%3}, {%4,%5,%6,%7}, {%8,%9}, {%0,%1,%2,%3};"
        : "+f"(d0), "+f"(d1), "+f"(d2), "+f"(d3)
        : "r"(a0), "r"(a1), "r"(a2), "r"(a3), "r"(b0), "r"(b1));
}

// f[10] = {fx,fy,fr,fg,fb,h,s0,s1,s2,s3}; features pre-scaled by sqrt(log2 e),
// h = -0.5*||f_scaled||^2 so exp(-0.5 d^2) == ex2(h_p + h_q + f_p.f_q).
__device__ __forceinline__ void compute_pt(const float* __restrict__ img,
                                           const float* __restrict__ sg,
                                           int p, float* f) {
    const float SQL2E = 1.2011224087864498f;
    int y = p >> 6, x = p & 63;
    int ro = (y << 8) + (x << 1);
    float fx = (float)x * (SQL2E / 50.0f);
    float fy = (float)y * (SQL2E / 50.0f);
    float fr = img[ro]         * (SQL2E / 15.0f);
    float fg = img[16384 + ro] * (SQL2E / 15.0f);
    float fb = img[32768 + ro] * (SQL2E / 15.0f);
    float h  = -0.5f * (fx*fx + fy*fy + fr*fr + fg*fg + fb*fb);
    f[0]=fx; f[1]=fy; f[2]=fr; f[3]=fg; f[4]=fb; f[5]=h;
#pragma unroll
    for (int k = 0; k < 4; k++) {
        const float* sk = sg + k * 16384;
        f[6+k] = (sk[ro] + sk[ro+1] + sk[ro+128] + sk[ro+129]) * 0.25f;
    }
}

__global__ void __launch_bounds__(BLOCK) crf_kernel(const float* __restrict__ images,
                                                    const float* __restrict__ segs,
                                                    float* __restrict__ out) {
    __shared__ float sFA[SLOTS * FSTR];   // p-tile slots (10.9 KB)
    __shared__ float sFB[SLOTS * FSTR];   // q-tile slots
    __shared__ float sHA[PTILE];          // h_p, full fp32
    __shared__ float sHB[PTILE];          // h_q
    __shared__ float wsum[BLOCK / 32];

    int tid  = threadIdx.x;
    int w    = tid >> 5;
    int lane = tid & 31;
    int g    = lane & 3;    // frag column group
    int r    = lane >> 2;   // frag row
    int n = blockIdx.y;

    // decode upper-triangle cell t -> (I, J), J >= I
    int t = blockIdx.x;
    float ft = (float)t;
    int I = (int)((2.0f*NTILES + 1.0f - sqrtf((2.0f*NTILES+1.0f)*(2.0f*NTILES+1.0f) - 8.0f*ft)) * 0.5f);
    while (I * NTILES - (I * (I - 1)) / 2 > t) I--;
    while ((I + 1) * NTILES - ((I + 1) * I) / 2 <= t) I++;
    int J = I + (t - (I * NTILES - (I * (I - 1)) / 2));

    const float* img = images + (size_t)n * 3 * 16384;
    const float* sg  = segs   + (size_t)n * 4 * 16384;

    // ---- fill: each thread builds one p-point (A layout) and one q-point (B layout) ----
    // D-slots (K=16): A: 0-4 p_hi, 5-9 p_hi, 10-14 p_lo, 15 0
    //                 B: 0-4 q_hi, 5-9 q_lo, 10-14 q_hi, 15 0
    // G-slots 16-19: seg vector (tf32). h enters at c-init (full fp32).
    {
        float f[10];
        compute_pt(img, sg, I * PTILE + tid, f);
        float hi[5], lo[5];
#pragma unroll
        for (int d = 0; d < 5; d++) { hi[d] = tf32r(f[d]); lo[d] = tf32r(f[d] - hi[d]); }
#pragma unroll
        for (int d = 0; d < 5; d++) {
            sFA[d * FSTR + tid]        = hi[d];
            sFA[(5 + d) * FSTR + tid]  = hi[d];
            sFA[(10 + d) * FSTR + tid] = lo[d];
        }
        sFA[15 * FSTR + tid] = 0.0f;
        sHA[tid] = f[5];
#pragma unroll
        for (int k = 0; k < 4; k++)
            sFA[(16 + k) * FSTR + tid] = tf32r(f[6 + k]);
    }
    {
        float f[10];
        compute_pt(img, sg, J * PTILE + tid, f);
        float hi[5], lo[5];
#pragma unroll
        for (int d = 0; d < 5; d++) { hi[d] = tf32r(f[d]); lo[d] = tf32r(f[d] - hi[d]); }
#pragma unroll
        for (int d = 0; d < 5; d++) {
            sFB[d * FSTR + tid]        = hi[d];
            sFB[(5 + d) * FSTR + tid]  = lo[d];
            sFB[(10 + d) * FSTR + tid] = hi[d];
        }
        sFB[15 * FSTR + tid] = 0.0f;
        sHB[tid] = f[5];
#pragma unroll
        for (int k = 0; k < 4; k++)
            sFB[(16 + k) * FSTR + tid] = tf32r(f[6 + k]);
    }
    __syncthreads();

    // ---- per-warp: 32 p-rows (two m16 row-blocks at base, base+16), all q in 16 n-chunks ----
    int base = 32 * w;

    uint32_t A0[2][4], A1[2][4];
#pragma unroll
    for (int ks = 0; ks < 2; ks++) {
        int k0 = 8 * ks;
        A0[ks][0] = __float_as_uint(sFA[(k0 + g) * FSTR + base + r]);
        A0[ks][1] = __float_as_uint(sFA[(k0 + g) * FSTR + base + r + 8]);
        A0[ks][2] = __float_as_uint(sFA[(k0 + g + 4) * FSTR + base + r]);
        A0[ks][3] = __float_as_uint(sFA[(k0 + g + 4) * FSTR + base + r + 8]);
        A1[ks][0] = __float_as_uint(sFA[(k0 + g) * FSTR + base + 16 + r]);
        A1[ks][1] = __float_as_uint(sFA[(k0 + g) * FSTR + base + 16 + r + 8]);
        A1[ks][2] = __float_as_uint(sFA[(k0 + g + 4) * FSTR + base + 16 + r]);
        A1[ks][3] = __float_as_uint(sFA[(k0 + g + 4) * FSTR + base + 16 + r + 8]);
    }
    uint32_t GA00 = __float_as_uint(sFA[(16 + g) * FSTR + base + r]);
    uint32_t GA01 = __float_as_uint(sFA[(16 + g) * FSTR + base + r + 8]);
    uint32_t GA10 = __float_as_uint(sFA[(16 + g) * FSTR + base + 16 + r]);
    uint32_t GA11 = __float_as_uint(sFA[(16 + g) * FSTR + base + 16 + r + 8]);

    float hp0 = sHA[base + r];
    float hp1 = sHA[base + r + 8];
    float hp2 = sHA[base + 16 + r];
    float hp3 = sHA[base + 16 + r + 8];

    float ac0 = 0.f, ac1 = 0.f, ac2 = 0.f, ac3 = 0.f;

#pragma unroll 2
    for (int j = 0; j < 16; j++) {
        int n0 = 8 * j;

        // B-side fragments, shared by both row-blocks
        uint32_t b00 = __float_as_uint(sFB[(g) * FSTR + n0 + r]);
        uint32_t b01 = __float_as_uint(sFB[(g + 4) * FSTR + n0 + r]);
        uint32_t b10 = __float_as_uint(sFB[(8 + g) * FSTR + n0 + r]);
        uint32_t b11 = __float_as_uint(sFB[(12 + g) * FSTR + n0 + r]);
        uint32_t gb  = __float_as_uint(sFB[(16 + g) * FSTR + n0 + r]);
        float2 hq = *(const float2*)&sHB[n0 + 2 * g];

        // row-block 0
        {
            float d0 = hp0 + hq.x, d1 = hp0 + hq.y, d2 = hp1 + hq.x, d3 = hp1 + hq.y;
            mma8(d0, d1, d2, d3, A0[0][0], A0[0][1], A0[0][2], A0[0][3], b00, b01);
            mma8(d0, d1, d2, d3, A0[1][0], A0[1][1], A0[1][2], A0[1][3], b10, b11);
            float g0 = 0.f, g1 = 0.f, g2 = 0.f, g3 = 0.f;
            mma8(g0, g1, g2, g3, GA00, GA01, 0u, 0u, gb, 0u);
            ac0 = fmaf(ex2f(d0), g0, ac0);
            ac1 = fmaf(ex2f(d1), g1, ac1);
            ac0 = fmaf(ex2f(d2), g2, ac0);
            ac1 = fmaf(ex2f(d3), g3, ac1);
        }
        // row-block 1 (same B fragments)
        {
            float d0 = hp2 + hq.x, d1 = hp2 + hq.y, d2 = hp3 + hq.x, d3 = hp3 + hq.y;
            mma8(d0, d1, d2, d3, A1[0][0], A1[0][1], A1[0][2], A1[0][3], b00, b01);
            mma8(d0, d1, d2, d3, A1[1][0], A1[1][1], A1[1][2], A1[1][3], b10, b11);
            float g0 = 0.f, g1 = 0.f, g2 = 0.f, g3 = 0.f;
            mma8(g0, g1, g2, g3, GA10, GA11, 0u, 0u, gb, 0u);
            ac2 = fmaf(ex2f(d0), g0, ac2);
            ac3 = fmaf(ex2f(d1), g1, ac3);
            ac2 = fmaf(ex2f(d2), g2, ac2);
            ac3 = fmaf(ex2f(d3), g3, ac3);
        }
    }

    float acc = (ac0 + ac1) + (ac2 + ac3);
    if (I != J) acc *= 2.0f;   // symmetric off-diagonal cell

    // warp + block reduce, one double atomic per block
#pragma unroll
    for (int off = 16; off > 0; off >>= 1)
        acc += __shfl_down_sync(0xFFFFFFFFu, acc, off);
    if (lane == 0) wsum[w] = acc;
    __syncthreads();
    if (tid == 0) {
        float s = (wsum[0] + wsum[1]) + (wsum[2] + wsum[3]);
        atomicAdd(&g_acc, (double)s);
        __threadfence();
        unsigned int d = atomicAdd(&g_done, 1u);
        if (d == TOTALB - 1u) {
            double total = *((volatile double*)&g_acc);
            out[0] = (float)(total * (-1e-7 / (double)N_BATCH));
            g_acc = 0.0;          // reset for next graph replay
            g_done = 0u;
        }
    }
}

extern "C" void kernel_launch(void* const* d_in, const int* in_sizes, int n_in,
                              void* d_out, int out_size) {
    const float* images = (const float*)d_in[0];
    const float* segs   = (const float*)d_in[1];
    dim3 grid(CELLS, N_BATCH);
    crf_kernel<<<grid, BLOCK>>>(images, segs, (float*)d_out);
}